// round 1
// baseline (speedup 1.0000x reference)
#include <cuda_runtime.h>
#include <math.h>
#include <float.h>

// Problem-fixed maxima (shapes are fixed for this dataset)
#define NMAX 20000
#define EMAX 200000
#define PMAX 800000

// ---------------- scratch (device globals; no allocation allowed) ----------
__device__ float g_bufA[NMAX * 512];          // xl (layer1 then layer2)
__device__ float g_bufB[NMAX * 512];          // GAT1 aggregation / x1
__device__ float g_final[NMAX * 1536];        // [x2 | left | right]
__device__ float g_hc[NMAX * 512];            // classifier hidden
__device__ float g_s[NMAX * 8];
__device__ float g_d[NMAX * 8];
__device__ float g_amax[NMAX * 8];
__device__ float g_den[NMAX * 8];
__device__ float g_ex[(EMAX + NMAX) * 8];     // alpha -> exp storage
__device__ float g_xp[EMAX * 6];              // per-edge max-pooled synapse
__device__ float g_h1[EMAX * 256];            // synapse MLP hidden
__device__ float g_xp2[EMAX * 512];           // synapse MLP out
__device__ float g_cntL[NMAX];
__device__ float g_cntR[NMAX];

// ---------------- helpers ---------------------------------------------------
__device__ __forceinline__ void atomicMaxF(float* addr, float val) {
    int* ai = (int*)addr;
    int old = *ai;
    while (__int_as_float(old) < val) {
        int assumed = old;
        old = atomicCAS(ai, assumed, __float_as_int(val));
        if (old == assumed) break;
    }
}

__global__ void fill_f(float* p, float v, int n) {
    int i = blockIdx.x * blockDim.x + threadIdx.x;
    if (i < n) p[i] = v;
}

// p[r*ld + off + c] = bias ? bias[c] : 0
__global__ void init_rows_bias(float* p, const float* bias, int rows, int cols, int ld, int off) {
    int i = blockIdx.x * blockDim.x + threadIdx.x;
    if (i >= rows * cols) return;
    int r = i / cols, c = i % cols;
    p[r * ld + off + c] = bias ? bias[c] : 0.f;
}

// ---------------- tiled SGEMM: C = act(A[M,K] @ B[K,N] + bias) --------------
// act: 0=none, 1=relu
__global__ void sgemm_kernel(const float* __restrict__ A, const float* __restrict__ B,
                             const float* __restrict__ bias, float* __restrict__ C,
                             int M, int N, int K, int act) {
    const int BM = 64, BN = 64, BK = 16;
    __shared__ float As[BK][BM + 1];
    __shared__ float Bs[BK][BN + 1];
    int tid = threadIdx.x;  // 256 threads
    int blockRow = blockIdx.y * BM, blockCol = blockIdx.x * BN;
    int tr = tid / 16, tc = tid % 16;
    float acc[4][4] = {};
    for (int k0 = 0; k0 < K; k0 += BK) {
        for (int i = tid; i < BM * BK; i += 256) {
            int r = i / BK, c = i % BK;
            int gr = blockRow + r, gc = k0 + c;
            As[c][r] = (gr < M && gc < K) ? A[(size_t)gr * K + gc] : 0.f;
        }
        for (int i = tid; i < BK * BN; i += 256) {
            int r = i / BN, c = i % BN;
            int gr = k0 + r, gc = blockCol + c;
            Bs[r][c] = (gr < K && gc < N) ? B[(size_t)gr * N + gc] : 0.f;
        }
        __syncthreads();
#pragma unroll
        for (int k = 0; k < BK; k++) {
            float a[4], b[4];
#pragma unroll
            for (int i = 0; i < 4; i++) a[i] = As[k][tr * 4 + i];
#pragma unroll
            for (int j = 0; j < 4; j++) b[j] = Bs[k][tc * 4 + j];
#pragma unroll
            for (int i = 0; i < 4; i++)
#pragma unroll
                for (int j = 0; j < 4; j++) acc[i][j] += a[i] * b[j];
        }
        __syncthreads();
    }
    for (int i = 0; i < 4; i++) {
        int gr = blockRow + tr * 4 + i;
        if (gr >= M) continue;
        for (int j = 0; j < 4; j++) {
            int gc = blockCol + tc * 4 + j;
            if (gc >= N) continue;
            float v = acc[i][j] + (bias ? bias[gc] : 0.f);
            if (act == 1) v = fmaxf(v, 0.f);
            C[(size_t)gr * N + gc] = v;
        }
    }
}

// ---------------- GAT pieces ------------------------------------------------
// s[n,h] = <xl[n,h,:], att_src[h,:]> ; d likewise. One warp per (n,h).
__global__ void sd_kernel(const float* __restrict__ xl, const float* __restrict__ asr,
                          const float* __restrict__ adt, float* __restrict__ s,
                          float* __restrict__ d, int n, int H, int C) {
    int warp = (blockIdx.x * blockDim.x + threadIdx.x) >> 5;
    int lane = threadIdx.x & 31;
    if (warp >= n * H) return;
    int node = warp / H, h = warp % H;
    const float* row = xl + (size_t)node * H * C + (size_t)h * C;
    float ss = 0.f, dd = 0.f;
    for (int c = lane; c < C; c += 32) {
        float v = row[c];
        ss += v * asr[h * C + c];
        dd += v * adt[h * C + c];
    }
#pragma unroll
    for (int o = 16; o; o >>= 1) {
        ss += __shfl_down_sync(~0u, ss, o);
        dd += __shfl_down_sync(~0u, dd, o);
    }
    if (!lane) { s[warp] = ss; d[warp] = dd; }
}

// alpha = leaky_relu(s[src]+d[dst]); store; atomicMax per (dst,h).
// Edges e<E come from edge_index, e>=E are self-loops (node e-E).
__global__ void alpha_max_kernel(const int* __restrict__ ei, const float* __restrict__ s,
                                 const float* __restrict__ d, float* __restrict__ ex,
                                 float* __restrict__ amax, int E, int n, int H) {
    int idx = blockIdx.x * blockDim.x + threadIdx.x;
    int tot = (E + n) * H;
    if (idx >= tot) return;
    int e = idx / H, h = idx - e * H;
    int sN = (e < E) ? ei[e] : (e - E);
    int dN = (e < E) ? ei[E + e] : (e - E);
    float a = s[sN * H + h] + d[dN * H + h];
    a = a > 0.f ? a : 0.2f * a;
    ex[idx] = a;
    atomicMaxF(&amax[dN * H + h], a);
}

__global__ void exp_sum_kernel(const int* __restrict__ ei, float* __restrict__ ex,
                               const float* __restrict__ amax, float* __restrict__ den,
                               int E, int n, int H) {
    int idx = blockIdx.x * blockDim.x + threadIdx.x;
    int tot = (E + n) * H;
    if (idx >= tot) return;
    int e = idx / H, h = idx - e * H;
    int dN = (e < E) ? ei[E + e] : (e - E);
    float v = expf(ex[idx] - amax[dN * H + h]);
    ex[idx] = v;
    atomicAdd(&den[dN * H + h], v);
}

// out[dst, c] += xl[src, c] * ex[e,h]/(den[dst,h]+eps)
__global__ void aggregate_kernel(const int* __restrict__ ei, const float* __restrict__ xl,
                                 const float* __restrict__ ex, const float* __restrict__ den,
                                 float* __restrict__ out, int ldout,
                                 int E, int n, int H, int C) {
    int HC = H * C;
    long long idx = (long long)blockIdx.x * blockDim.x + threadIdx.x;
    long long tot = (long long)(E + n) * HC;
    if (idx >= tot) return;
    int e = (int)(idx / HC);
    int c = (int)(idx - (long long)e * HC);
    int h = c / C;
    int sN = (e < E) ? ei[e] : (e - E);
    int dN = (e < E) ? ei[E + e] : (e - E);
    float a = ex[(size_t)e * H + h] / (den[dN * H + h] + 1e-16f);
    atomicAdd(&out[(size_t)dN * ldout + c], xl[(size_t)sN * HC + c] * a);
}

__global__ void elu_kernel(float* p, int n) {
    int i = blockIdx.x * blockDim.x + threadIdx.x;
    if (i >= n) return;
    float v = p[i];
    p[i] = v > 0.f ? v : expm1f(v);
}

// ---------------- synapse branch -------------------------------------------
__global__ void synapse_max_kernel(const float* __restrict__ syn, const int* __restrict__ sidx,
                                   float* __restrict__ xp, int P) {
    long long idx = (long long)blockIdx.x * blockDim.x + threadIdx.x;
    if (idx >= (long long)P * 6) return;
    int p = (int)(idx / 6), f = (int)(idx - (long long)p * 6);
    int seg = sidx[p];
    atomicMaxF(&xp[seg * 6 + f], syn[(size_t)p * 6 + f]);
}

// h1 = relu(xp[E,6] @ We1[6,256] + be1)
__global__ void mlp1_kernel(const float* __restrict__ xp, const float* __restrict__ We1,
                            const float* __restrict__ be1, float* __restrict__ h1, int E) {
    long long idx = (long long)blockIdx.x * blockDim.x + threadIdx.x;
    if (idx >= (long long)E * 256) return;
    int r = (int)(idx / 256), c = (int)(idx - (long long)r * 256);
    float sum = be1[c];
#pragma unroll
    for (int f = 0; f < 6; f++) sum += __ldg(&xp[r * 6 + f]) * __ldg(&We1[f * 256 + c]);
    h1[idx] = fmaxf(sum, 0.f);
}

__global__ void edge_count_kernel(const int* __restrict__ ei, float* cntL, float* cntR, int E) {
    int e = blockIdx.x * blockDim.x + threadIdx.x;
    if (e >= E) return;
    atomicAdd(&cntL[ei[e]], 1.f);
    atomicAdd(&cntR[ei[E + e]], 1.f);
}

// scatter xp2 into final[:,512:1024] (by src) and final[:,1024:1536] (by dst)
__global__ void scatter_sum_kernel(const int* __restrict__ ei, const float* __restrict__ xp2,
                                   float* __restrict__ fin, int E) {
    long long idx = (long long)blockIdx.x * blockDim.x + threadIdx.x;
    if (idx >= (long long)E * 512) return;
    int e = (int)(idx / 512), c = (int)(idx - (long long)e * 512);
    float v = xp2[idx];
    atomicAdd(&fin[(size_t)ei[e] * 1536 + 512 + c], v);
    atomicAdd(&fin[(size_t)ei[E + e] * 1536 + 1024 + c], v);
}

__global__ void divide_kernel(float* __restrict__ fin, const float* __restrict__ cntL,
                              const float* __restrict__ cntR, int n) {
    long long idx = (long long)blockIdx.x * blockDim.x + threadIdx.x;
    if (idx >= (long long)n * 1024) return;
    int r = (int)(idx / 1024), c = (int)(idx - (long long)r * 1024);
    if (c < 512) fin[(size_t)r * 1536 + 512 + c] /= fmaxf(cntL[r], 1.f);
    else fin[(size_t)r * 1536 + 1024 + (c - 512)] /= fmaxf(cntR[r], 1.f);
}

// ---------------- host ------------------------------------------------------
static inline int g1(long long total) { return (int)((total + 255) / 256); }

extern "C" void kernel_launch(void* const* d_in, const int* in_sizes, int n_in,
                              void* d_out, int out_size) {
    const int*   ei   = (const int*)d_in[0];
    const float* syn  = (const float*)d_in[2];
    const int*   sidx = (const int*)d_in[3];
    const float* x_p  = (const float*)d_in[5];
    const float* W1   = (const float*)d_in[6];
    const float* as1  = (const float*)d_in[7];
    const float* ad1  = (const float*)d_in[8];
    const float* b1   = (const float*)d_in[9];
    const float* W2   = (const float*)d_in[10];
    const float* as2  = (const float*)d_in[11];
    const float* ad2  = (const float*)d_in[12];
    const float* b2   = (const float*)d_in[13];
    const float* We1  = (const float*)d_in[14];
    const float* be1  = (const float*)d_in[15];
    const float* We2  = (const float*)d_in[16];
    const float* be2  = (const float*)d_in[17];
    const float* Wc1  = (const float*)d_in[18];
    const float* bc1  = (const float*)d_in[19];
    const float* Wc2  = (const float*)d_in[20];
    const float* bc2  = (const float*)d_in[21];

    const int E = in_sizes[0] / 2;
    const int P = in_sizes[2] / 6;
    const int N = in_sizes[5] / 128;
    const int NCLS = in_sizes[20] / 512;
    float* out = (float*)d_out;

    float *bufA, *bufB, *fin, *hc, *s, *d, *amax, *den, *ex, *xp, *h1, *xp2, *cntL, *cntR;
    cudaGetSymbolAddress((void**)&bufA, g_bufA);
    cudaGetSymbolAddress((void**)&bufB, g_bufB);
    cudaGetSymbolAddress((void**)&fin,  g_final);
    cudaGetSymbolAddress((void**)&hc,   g_hc);
    cudaGetSymbolAddress((void**)&s,    g_s);
    cudaGetSymbolAddress((void**)&d,    g_d);
    cudaGetSymbolAddress((void**)&amax, g_amax);
    cudaGetSymbolAddress((void**)&den,  g_den);
    cudaGetSymbolAddress((void**)&ex,   g_ex);
    cudaGetSymbolAddress((void**)&xp,   g_xp);
    cudaGetSymbolAddress((void**)&h1,   g_h1);
    cudaGetSymbolAddress((void**)&xp2,  g_xp2);
    cudaGetSymbolAddress((void**)&cntL, g_cntL);
    cudaGetSymbolAddress((void**)&cntR, g_cntR);

    dim3 blk(256);

    // ===== GAT layer 1 =====
    {
        dim3 grid(512 / 64, (N + 63) / 64);
        sgemm_kernel<<<grid, blk>>>(x_p, W1, nullptr, bufA, N, 512, 128, 0);  // xl1
    }
    sd_kernel<<<g1((long long)N * 8 * 32), blk>>>(bufA, as1, ad1, s, d, N, 8, 64);
    fill_f<<<g1(N * 8), blk>>>(amax, -FLT_MAX, N * 8);
    fill_f<<<g1(N * 8), blk>>>(den, 0.f, N * 8);
    init_rows_bias<<<g1((long long)N * 512), blk>>>(bufB, b1, N, 512, 512, 0);
    alpha_max_kernel<<<g1((long long)(E + N) * 8), blk>>>(ei, s, d, ex, amax, E, N, 8);
    exp_sum_kernel<<<g1((long long)(E + N) * 8), blk>>>(ei, ex, amax, den, E, N, 8);
    aggregate_kernel<<<g1((long long)(E + N) * 512), blk>>>(ei, bufA, ex, den, bufB, 512, E, N, 8, 64);
    elu_kernel<<<g1((long long)N * 512), blk>>>(bufB, N * 512);

    // ===== GAT layer 2 (H=1, C=512) =====
    {
        dim3 grid(512 / 64, (N + 63) / 64);
        sgemm_kernel<<<grid, blk>>>(bufB, W2, nullptr, bufA, N, 512, 512, 0);  // xl2
    }
    sd_kernel<<<g1((long long)N * 32), blk>>>(bufA, as2, ad2, s, d, N, 1, 512);
    fill_f<<<g1(N), blk>>>(amax, -FLT_MAX, N);
    fill_f<<<g1(N), blk>>>(den, 0.f, N);
    init_rows_bias<<<g1((long long)N * 512), blk>>>(fin, b2, N, 512, 1536, 0);
    init_rows_bias<<<g1((long long)N * 1024), blk>>>(fin, nullptr, N, 1024, 1536, 512);
    alpha_max_kernel<<<g1((long long)(E + N)), blk>>>(ei, s, d, ex, amax, E, N, 1);
    exp_sum_kernel<<<g1((long long)(E + N)), blk>>>(ei, ex, amax, den, E, N, 1);
    aggregate_kernel<<<g1((long long)(E + N) * 512), blk>>>(ei, bufA, ex, den, fin, 1536, E, N, 1, 512);

    // ===== synapse branch =====
    fill_f<<<g1(E * 6), blk>>>(xp, -FLT_MAX, E * 6);
    synapse_max_kernel<<<g1((long long)P * 6), blk>>>(syn, sidx, xp, P);
    mlp1_kernel<<<g1((long long)E * 256), blk>>>(xp, We1, be1, h1, E);
    {
        dim3 grid(512 / 64, (E + 63) / 64);
        sgemm_kernel<<<grid, blk>>>(h1, We2, be2, xp2, E, 512, 256, 0);
    }
    fill_f<<<g1(N), blk>>>(cntL, 0.f, N);
    fill_f<<<g1(N), blk>>>(cntR, 0.f, N);
    edge_count_kernel<<<g1(E), blk>>>(ei, cntL, cntR, E);
    scatter_sum_kernel<<<g1((long long)E * 512), blk>>>(ei, xp2, fin, E);
    divide_kernel<<<g1((long long)N * 1024), blk>>>(fin, cntL, cntR, N);

    // ===== classifier =====
    {
        dim3 grid(512 / 64, (N + 63) / 64);
        sgemm_kernel<<<grid, blk>>>(fin, Wc1, bc1, hc, N, 512, 1536, 1);
    }
    {
        dim3 grid((NCLS + 63) / 64, (N + 63) / 64);
        sgemm_kernel<<<grid, blk>>>(hc, Wc2, bc2, out, N, NCLS, 512, 0);
    }
}

// round 2
// speedup vs baseline: 2.7500x; 2.7500x over previous
#include <cuda_runtime.h>
#include <math.h>
#include <float.h>

#define NMAX 20000
#define EMAX 200000

typedef unsigned long long ull;

// ---------------- scratch (device globals; no allocation allowed) ----------
__device__ float g_bufA[NMAX * 512];          // xl (layer1 then layer2)
__device__ float g_bufB[NMAX * 512];          // x1 (post GAT1 + ELU)
__device__ float g_fin[NMAX * 1536];          // [x2 | left | right]
__device__ float g_hc[NMAX * 512];            // classifier hidden
__device__ float g_s[NMAX * 8];
__device__ float g_d[NMAX * 8];
__device__ int   g_xpi[EMAX * 6];             // monotonic-int encoded max-pool
__device__ float g_xp2[EMAX * 512];           // synapse MLP out
__device__ int g_degA[NMAX], g_degL[NMAX], g_degR[NMAX];
__device__ int g_rowA[NMAX + 1], g_rowL[NMAX + 1], g_rowR[NMAX + 1];
__device__ int g_curA[NMAX], g_curL[NMAX], g_curR[NMAX];
__device__ int g_adjA[EMAX + NMAX];           // src node per dst-CSR entry
__device__ int g_eidL[EMAX], g_eidR[EMAX];
__device__ float g_wc2p[512 * 256];

// ---------------- monotonic float<->int for atomicMax ----------------------
__device__ __forceinline__ int mono_enc(float f) {
    int i = __float_as_int(f);
    return i >= 0 ? i : (i ^ 0x7FFFFFFF);
}
__device__ __forceinline__ float mono_dec(int i) {
    int j = i >= 0 ? i : (i ^ 0x7FFFFFFF);
    return __int_as_float(j);
}

// ---------------- f32x2 helpers --------------------------------------------
#define PACK2(d, x, y)   asm("mov.b64 %0, {%1, %2};" : "=l"(d) : "f"(x), "f"(y))
#define UNPACK2(x, y, d) asm("mov.b64 {%0, %1}, %2;" : "=f"(x), "=f"(y) : "l"(d))
#define FMA2(d, a, b)    asm("fma.rn.f32x2 %0, %1, %2, %0;" : "+l"(d) : "l"(a), "l"(b))

// ---------------- tiny utility kernels -------------------------------------
__global__ void fill_int(int* p, int v, int n) {
    int i = blockIdx.x * blockDim.x + threadIdx.x;
    if (i < n) p[i] = v;
}

__global__ void pad_wc2(const float* __restrict__ W, float* __restrict__ Wp, int ncls) {
    int i = blockIdx.x * blockDim.x + threadIdx.x;
    if (i >= 512 * 256) return;
    int r = i >> 8, c = i & 255;
    Wp[i] = (c < ncls) ? W[r * ncls + c] : 0.f;
}

// ---------------- CSR build -------------------------------------------------
__global__ void count_deg(const int* __restrict__ ei, int E, int n,
                          int* degA, int* degL, int* degR) {
    int e = blockIdx.x * blockDim.x + threadIdx.x;
    if (e < E) {
        int s = ei[e], d = ei[E + e];
        atomicAdd(&degA[d], 1);
        atomicAdd(&degL[s], 1);
        atomicAdd(&degR[d], 1);
    } else if (e < E + n) {
        atomicAdd(&degA[e - E], 1);   // self-loop
    }
}

// single-block exclusive scan; writes rowoff[0..n] and cursor copy
__global__ void scan_kernel(const int* __restrict__ deg, int* rowoff, int* cur, int n) {
    __shared__ int sh[1024];
    __shared__ int carry;
    int tid = threadIdx.x;
    if (tid == 0) carry = 0;
    __syncthreads();
    for (int base = 0; base < n; base += 1024) {
        int i = base + tid;
        int v = (i < n) ? deg[i] : 0;
        sh[tid] = v;
        __syncthreads();
        for (int off = 1; off < 1024; off <<= 1) {
            int t = (tid >= off) ? sh[tid - off] : 0;
            __syncthreads();
            sh[tid] += t;
            __syncthreads();
        }
        int excl = sh[tid] - v + carry;
        if (i < n) { rowoff[i] = excl; cur[i] = excl; }
        __syncthreads();
        if (tid == 1023) carry += sh[1023];
        __syncthreads();
    }
    if (tid == 0) rowoff[n] = carry;
}

__global__ void fill_adj(const int* __restrict__ ei, int E, int n,
                         int* curA, int* adjA, int* curL, int* eidL,
                         int* curR, int* eidR) {
    int e = blockIdx.x * blockDim.x + threadIdx.x;
    if (e < E) {
        int s = ei[e], d = ei[E + e];
        int p = atomicAdd(&curA[d], 1); adjA[p] = s;
        p = atomicAdd(&curL[s], 1); eidL[p] = e;
        p = atomicAdd(&curR[d], 1); eidR[p] = e;
    } else if (e < E + n) {
        int node = e - E;
        int p = atomicAdd(&curA[node], 1); adjA[p] = node;
    }
}

// ---------------- GEMM: C = act(A[M,K] @ B[K,N] + bias) --------------------
// 128x128 tile, BK=16, 256 threads, 8x8 microtile via fma.rn.f32x2.
// FUSED==1: A row r is relu(xp[r] @ We1 + be1) computed on the fly (K==256).
template<int FUSED>
__launch_bounds__(256)
__global__ void gemm128(const float* __restrict__ A, const float* __restrict__ B,
                        const float* __restrict__ bias, float* __restrict__ C,
                        int M, int N, int K, int Cld, int Nstore, int act,
                        const int* __restrict__ xpi,
                        const float* __restrict__ We1, const float* __restrict__ be1) {
    __shared__ float As[16][132];
    __shared__ float Bs[16][132];
    __shared__ float xps[128][6];

    const int tid = threadIdx.x;
    const int blockRow = blockIdx.y * 128, blockCol = blockIdx.x * 128;

    if constexpr (FUSED) {
        for (int i = tid; i < 128 * 6; i += 256) {
            int m = i / 6, f = i - m * 6;
            int gr = blockRow + m;
            xps[m][f] = (gr < M) ? mono_dec(xpi[(size_t)gr * 6 + f]) : 0.f;
        }
    }

    ull acc[4][8];
#pragma unroll
    for (int i = 0; i < 4; i++)
#pragma unroll
        for (int j = 0; j < 8; j++) acc[i][j] = 0ull;

    const int tr = tid >> 4, tc = tid & 15;
    const int m0 = tr * 8, n0 = tc * 8;

    for (int k0 = 0; k0 < K; k0 += 16) {
        __syncthreads();
        if constexpr (FUSED) {
            int kq = tid & 15, mb = tid >> 4;
            float w0 = __ldg(&We1[0 * 256 + k0 + kq]);
            float w1 = __ldg(&We1[1 * 256 + k0 + kq]);
            float w2 = __ldg(&We1[2 * 256 + k0 + kq]);
            float w3 = __ldg(&We1[3 * 256 + k0 + kq]);
            float w4 = __ldg(&We1[4 * 256 + k0 + kq]);
            float w5 = __ldg(&We1[5 * 256 + k0 + kq]);
            float bk = __ldg(&be1[k0 + kq]);
#pragma unroll
            for (int j = 0; j < 8; j++) {
                int m = mb + 16 * j;
                float v = bk + w0 * xps[m][0] + w1 * xps[m][1] + w2 * xps[m][2]
                             + w3 * xps[m][3] + w4 * xps[m][4] + w5 * xps[m][5];
                As[kq][m] = fmaxf(v, 0.f);
            }
        } else {
#pragma unroll
            for (int l = 0; l < 2; l++) {
                int m = (tid >> 2) + l * 64;
                int kq = (tid & 3) * 4;
                int gr = blockRow + m;
                float4 v = make_float4(0.f, 0.f, 0.f, 0.f);
                if (gr < M) v = *(const float4*)(A + (size_t)gr * K + k0 + kq);
                As[kq + 0][m] = v.x; As[kq + 1][m] = v.y;
                As[kq + 2][m] = v.z; As[kq + 3][m] = v.w;
            }
        }
#pragma unroll
        for (int l = 0; l < 2; l++) {
            int kr = (tid >> 5) + l * 8;
            int n4 = (tid & 31) * 4;
            float4 v = *(const float4*)(B + (size_t)(k0 + kr) * N + blockCol + n4);
            *(float4*)&Bs[kr][n4] = v;
        }
        __syncthreads();
#pragma unroll
        for (int k = 0; k < 16; k++) {
            float4 a0 = *(const float4*)&As[k][m0];
            float4 a1 = *(const float4*)&As[k][m0 + 4];
            float4 b0 = *(const float4*)&Bs[k][n0];
            float4 b1 = *(const float4*)&Bs[k][n0 + 4];
            ull a2[4], bb[8];
            PACK2(a2[0], a0.x, a0.y); PACK2(a2[1], a0.z, a0.w);
            PACK2(a2[2], a1.x, a1.y); PACK2(a2[3], a1.z, a1.w);
            PACK2(bb[0], b0.x, b0.x); PACK2(bb[1], b0.y, b0.y);
            PACK2(bb[2], b0.z, b0.z); PACK2(bb[3], b0.w, b0.w);
            PACK2(bb[4], b1.x, b1.x); PACK2(bb[5], b1.y, b1.y);
            PACK2(bb[6], b1.z, b1.z); PACK2(bb[7], b1.w, b1.w);
#pragma unroll
            for (int i = 0; i < 4; i++)
#pragma unroll
                for (int j = 0; j < 8; j++) FMA2(acc[i][j], a2[i], bb[j]);
        }
    }

#pragma unroll
    for (int i = 0; i < 4; i++) {
        int r0 = blockRow + m0 + 2 * i;
#pragma unroll
        for (int j = 0; j < 8; j++) {
            float lo, hi;
            UNPACK2(lo, hi, acc[i][j]);
            int gc = blockCol + n0 + j;
            if (gc < Nstore) {
                float bv = bias ? bias[gc] : 0.f;
                if (r0 < M) {
                    float v = lo + bv;
                    if (act) v = fmaxf(v, 0.f);
                    C[(size_t)r0 * Cld + gc] = v;
                }
                if (r0 + 1 < M) {
                    float v = hi + bv;
                    if (act) v = fmaxf(v, 0.f);
                    C[(size_t)(r0 + 1) * Cld + gc] = v;
                }
            }
        }
    }
}

// ---------------- GAT attention scalars -------------------------------------
__global__ void sd_kernel(const float* __restrict__ xl, const float* __restrict__ asr,
                          const float* __restrict__ adt, float* __restrict__ s,
                          float* __restrict__ d, int n, int H, int C) {
    int warp = (blockIdx.x * blockDim.x + threadIdx.x) >> 5;
    int lane = threadIdx.x & 31;
    if (warp >= n * H) return;
    int node = warp / H, h = warp - node * H;
    const float* row = xl + (size_t)node * H * C + (size_t)h * C;
    float ss = 0.f, dd = 0.f;
    for (int c = lane; c < C; c += 32) {
        float v = row[c];
        ss += v * asr[h * C + c];
        dd += v * adt[h * C + c];
    }
#pragma unroll
    for (int o = 16; o; o >>= 1) {
        ss += __shfl_down_sync(~0u, ss, o);
        dd += __shfl_down_sync(~0u, dd, o);
    }
    if (!lane) { s[warp] = ss; d[warp] = dd; }
}

// ---------------- GAT aggregation (CSR, atomic-free) ------------------------
// One block per dst node: segment softmax over incoming edges, weighted gather.
template<int H, int C>
__launch_bounds__(256)
__global__ void gat_agg(const int* __restrict__ row, const int* __restrict__ adj,
                        const float* __restrict__ s, const float* __restrict__ dvec,
                        const float* __restrict__ xl, const float* __restrict__ bias,
                        float* __restrict__ out, int ldout, int doElu) {
    constexpr int HC = H * C;
    constexpr int CAP = 512;
    constexpr int PT = (HC + 255) / 256;
    __shared__ float al[CAP * H];
    __shared__ int asrc[CAP];
    __shared__ float mh[8], zinv[8];

    int n = blockIdx.x, tid = threadIdx.x, w = tid >> 5, lane = tid & 31;
    int start = row[n], deg = row[n + 1] - start;

    // pass 1+2: warp w handles head w (recompute alpha from gmem; deg ~ 11)
    if (w < H) {
        float dh = dvec[n * H + w];
        float m = -FLT_MAX;
        for (int i = lane; i < deg; i += 32) {
            float a = s[adj[start + i] * H + w] + dh;
            a = a > 0.f ? a : 0.2f * a;
            m = fmaxf(m, a);
        }
#pragma unroll
        for (int o = 16; o; o >>= 1) m = fmaxf(m, __shfl_xor_sync(~0u, m, o));
        float z = 0.f;
        for (int i = lane; i < deg; i += 32) {
            float a = s[adj[start + i] * H + w] + dh;
            a = a > 0.f ? a : 0.2f * a;
            z += expf(a - m);
        }
#pragma unroll
        for (int o = 16; o; o >>= 1) z += __shfl_xor_sync(~0u, z, o);
        if (lane == 0) { mh[w] = m; zinv[w] = 1.f / (z + 1e-16f); }
    }
    __syncthreads();

    float acc[PT];
#pragma unroll
    for (int p = 0; p < PT; p++) {
        int c = tid + p * 256;
        acc[p] = (c < HC) ? bias[c] : 0.f;
    }

    for (int base = 0; base < deg; base += CAP) {
        int cnt = min(CAP, deg - base);
        __syncthreads();
        for (int i = tid; i < cnt; i += 256) asrc[i] = adj[start + base + i];
        __syncthreads();
        for (int i = tid; i < cnt * H; i += 256) {
            int e = i / H, h = i - e * H;
            float a = s[asrc[e] * H + h] + dvec[n * H + h];
            a = a > 0.f ? a : 0.2f * a;
            al[e * H + h] = expf(a - mh[h]) * zinv[h];
        }
        __syncthreads();
#pragma unroll
        for (int p = 0; p < PT; p++) {
            int c = tid + p * 256;
            if (c < HC) {
                int h = c / C;
                float a = acc[p];
                for (int i = 0; i < cnt; i++)
                    a += al[i * H + h] * xl[(size_t)asrc[i] * HC + c];
                acc[p] = a;
            }
        }
    }

#pragma unroll
    for (int p = 0; p < PT; p++) {
        int c = tid + p * 256;
        if (c < HC) {
            float v = acc[p];
            if (doElu) v = v > 0.f ? v : expm1f(v);
            out[(size_t)n * ldout + c] = v;
        }
    }
}

// ---------------- scatter-mean (CSR gather) ---------------------------------
__launch_bounds__(256)
__global__ void mean_gather(const int* __restrict__ row, const int* __restrict__ eid,
                            const float* __restrict__ xp2, float* __restrict__ fin,
                            int off) {
    __shared__ int eids[512];
    int n = blockIdx.x, tid = threadIdx.x;
    int start = row[n], deg = row[n + 1] - start;
    float a0 = 0.f, a1 = 0.f;
    for (int base = 0; base < deg; base += 512) {
        int cnt = min(512, deg - base);
        __syncthreads();
        for (int i = tid; i < cnt; i += 256) eids[i] = eid[start + base + i];
        __syncthreads();
        for (int i = 0; i < cnt; i++) {
            const float* r = xp2 + (size_t)eids[i] * 512;
            a0 += r[tid];
            a1 += r[tid + 256];
        }
    }
    float inv = 1.f / fmaxf((float)deg, 1.f);
    fin[(size_t)n * 1536 + off + tid] = a0 * inv;
    fin[(size_t)n * 1536 + off + tid + 256] = a1 * inv;
}

// ---------------- synapse max-pool ------------------------------------------
__global__ void synapse_max(const float* __restrict__ syn, const int* __restrict__ sidx,
                            int* __restrict__ xpi, int P) {
    int idx = blockIdx.x * blockDim.x + threadIdx.x;
    if (idx >= P * 6) return;
    int p = idx / 6, f = idx - p * 6;
    atomicMax(&xpi[(size_t)sidx[p] * 6 + f], mono_enc(syn[(size_t)p * 6 + f]));
}

// ---------------- host ------------------------------------------------------
static inline int g1(long long total) { return (int)((total + 255) / 256); }

extern "C" void kernel_launch(void* const* d_in, const int* in_sizes, int n_in,
                              void* d_out, int out_size) {
    const int*   ei   = (const int*)d_in[0];
    const float* syn  = (const float*)d_in[2];
    const int*   sidx = (const int*)d_in[3];
    const float* x_p  = (const float*)d_in[5];
    const float* W1   = (const float*)d_in[6];
    const float* as1  = (const float*)d_in[7];
    const float* ad1  = (const float*)d_in[8];
    const float* b1   = (const float*)d_in[9];
    const float* W2   = (const float*)d_in[10];
    const float* as2  = (const float*)d_in[11];
    const float* ad2  = (const float*)d_in[12];
    const float* b2   = (const float*)d_in[13];
    const float* We1  = (const float*)d_in[14];
    const float* be1  = (const float*)d_in[15];
    const float* We2  = (const float*)d_in[16];
    const float* be2  = (const float*)d_in[17];
    const float* Wc1  = (const float*)d_in[18];
    const float* bc1  = (const float*)d_in[19];
    const float* Wc2  = (const float*)d_in[20];
    const float* bc2  = (const float*)d_in[21];

    const int E = in_sizes[0] / 2;
    const int P = in_sizes[2] / 6;
    const int N = in_sizes[5] / 128;
    const int NCLS = in_sizes[20] / 512;
    float* out = (float*)d_out;

    float *bufA, *bufB, *fin, *hc, *s, *d, *xp2, *wc2p;
    int *xpi, *degA, *degL, *degR, *rowA, *rowL, *rowR, *curA, *curL, *curR,
        *adjA, *eidL, *eidR;
    cudaGetSymbolAddress((void**)&bufA, g_bufA);
    cudaGetSymbolAddress((void**)&bufB, g_bufB);
    cudaGetSymbolAddress((void**)&fin,  g_fin);
    cudaGetSymbolAddress((void**)&hc,   g_hc);
    cudaGetSymbolAddress((void**)&s,    g_s);
    cudaGetSymbolAddress((void**)&d,    g_d);
    cudaGetSymbolAddress((void**)&xpi,  g_xpi);
    cudaGetSymbolAddress((void**)&xp2,  g_xp2);
    cudaGetSymbolAddress((void**)&degA, g_degA);
    cudaGetSymbolAddress((void**)&degL, g_degL);
    cudaGetSymbolAddress((void**)&degR, g_degR);
    cudaGetSymbolAddress((void**)&rowA, g_rowA);
    cudaGetSymbolAddress((void**)&rowL, g_rowL);
    cudaGetSymbolAddress((void**)&rowR, g_rowR);
    cudaGetSymbolAddress((void**)&curA, g_curA);
    cudaGetSymbolAddress((void**)&curL, g_curL);
    cudaGetSymbolAddress((void**)&curR, g_curR);
    cudaGetSymbolAddress((void**)&adjA, g_adjA);
    cudaGetSymbolAddress((void**)&eidL, g_eidL);
    cudaGetSymbolAddress((void**)&eidR, g_eidR);
    cudaGetSymbolAddress((void**)&wc2p, g_wc2p);

    // ===== CSR build =====
    fill_int<<<g1(N), 256>>>(degA, 0, N);
    fill_int<<<g1(N), 256>>>(degL, 0, N);
    fill_int<<<g1(N), 256>>>(degR, 0, N);
    count_deg<<<g1(E + N), 256>>>(ei, E, N, degA, degL, degR);
    scan_kernel<<<1, 1024>>>(degA, rowA, curA, N);
    scan_kernel<<<1, 1024>>>(degL, rowL, curL, N);
    scan_kernel<<<1, 1024>>>(degR, rowR, curR, N);
    fill_adj<<<g1(E + N), 256>>>(ei, E, N, curA, adjA, curL, eidL, curR, eidR);

    // ===== synapse branch (independent) =====
    fill_int<<<g1((long long)E * 6), 256>>>(xpi, 0x80800000, E * 6);
    synapse_max<<<g1((long long)P * 6), 256>>>(syn, sidx, xpi, P);
    {   // fused: xp2 = (relu(decode(xpi)@We1+be1)) @ We2 + be2
        dim3 g(4, (E + 127) / 128);
        gemm128<1><<<g, 256>>>(nullptr, We2, be2, xp2, E, 512, 256, 512, 512, 0,
                               xpi, We1, be1);
    }

    // ===== GAT layer 1 =====
    {
        dim3 g(4, (N + 127) / 128);
        gemm128<0><<<g, 256>>>(x_p, W1, nullptr, bufA, N, 512, 128, 512, 512, 0,
                               nullptr, nullptr, nullptr);
    }
    sd_kernel<<<g1((long long)N * 8 * 32), 256>>>(bufA, as1, ad1, s, d, N, 8, 64);
    gat_agg<8, 64><<<N, 256>>>(rowA, adjA, s, d, bufA, b1, bufB, 512, 1);

    // ===== GAT layer 2 =====
    {
        dim3 g(4, (N + 127) / 128);
        gemm128<0><<<g, 256>>>(bufB, W2, nullptr, bufA, N, 512, 512, 512, 512, 0,
                               nullptr, nullptr, nullptr);
    }
    sd_kernel<<<g1((long long)N * 32), 256>>>(bufA, as2, ad2, s, d, N, 1, 512);
    gat_agg<1, 512><<<N, 256>>>(rowA, adjA, s, d, bufA, b2, fin, 1536, 0);

    // ===== scatter means into fin[:,512:1536] =====
    mean_gather<<<N, 256>>>(rowL, eidL, xp2, fin, 512);
    mean_gather<<<N, 256>>>(rowR, eidR, xp2, fin, 1024);

    // ===== classifier =====
    {
        dim3 g(4, (N + 127) / 128);
        gemm128<0><<<g, 256>>>(fin, Wc1, bc1, hc, N, 512, 1536, 512, 512, 1,
                               nullptr, nullptr, nullptr);
    }
    pad_wc2<<<g1(512 * 256), 256>>>(Wc2, wc2p, NCLS);
    {
        dim3 g(2, (N + 127) / 128);
        gemm128<0><<<g, 256>>>(hc, wc2p, bc2, out, N, 256, 512, NCLS, NCLS, 0,
                               nullptr, nullptr, nullptr);
    }
}

// round 6
// speedup vs baseline: 4.7732x; 1.7357x over previous
#include <cuda_runtime.h>
#include <cuda_bf16.h>
#include <math.h>
#include <float.h>

#define NMAX 20000
#define EMAX 200000

typedef unsigned long long ull;
typedef unsigned int u32;

// ---------------- scratch (device globals; no allocation allowed) ----------
__device__ float g_bufA[NMAX * 512];
__device__ float g_bufB[NMAX * 512];
__device__ float g_fin[NMAX * 1536];
__device__ float g_hc[NMAX * 512];
__device__ float g_s[NMAX * 8];
__device__ float g_d[NMAX * 8];
__device__ int   g_xpi[EMAX * 6];
__device__ float g_xp2[EMAX * 512];
__device__ int g_degA[NMAX], g_degL[NMAX], g_degR[NMAX];
__device__ int g_rowA[NMAX + 1], g_rowL[NMAX + 1], g_rowR[NMAX + 1];
__device__ int g_curA[NMAX], g_curL[NMAX], g_curR[NMAX];
__device__ int g_adjA[EMAX + NMAX];
__device__ int g_eidL[EMAX], g_eidR[EMAX];
// bf16 split weights, transposed to [N][K]
__device__ __nv_bfloat16 g_w1h[512 * 128],  g_w1l[512 * 128];
__device__ __nv_bfloat16 g_w2h[512 * 512],  g_w2l[512 * 512];
__device__ __nv_bfloat16 g_we2h[512 * 256], g_we2l[512 * 256];
__device__ __nv_bfloat16 g_wc1h[512 * 1536], g_wc1l[512 * 1536];
__device__ __nv_bfloat16 g_wc2h[256 * 512], g_wc2l[256 * 512];

// ---------------- PTX helpers (baseline ISA only; no tcgen05) ---------------
__device__ __forceinline__ u32 smem_u32(const void* p) {
    u32 a;
    asm("{ .reg .u64 t; cvta.to.shared.u64 t, %1; cvt.u32.u64 %0, t; }" : "=r"(a) : "l"(p));
    return a;
}
#define LDSM4(r, addr) \
    asm volatile("ldmatrix.sync.aligned.m8n8.x4.shared.b16 {%0,%1,%2,%3}, [%4];" \
        : "=r"((r)[0]), "=r"((r)[1]), "=r"((r)[2]), "=r"((r)[3]) : "r"(addr))
#define MMA16816(c, a, b0, b1) \
    asm volatile("mma.sync.aligned.m16n8k16.row.col.f32.bf16.bf16.f32 " \
        "{%0,%1,%2,%3}, {%4,%5,%6,%7}, {%8,%9}, {%0,%1,%2,%3};" \
        : "+f"((c)[0]), "+f"((c)[1]), "+f"((c)[2]), "+f"((c)[3]) \
        : "r"((a)[0]), "r"((a)[1]), "r"((a)[2]), "r"((a)[3]), "r"(b0), "r"(b1))
#define CP_ASYNC16(s, g) \
    asm volatile("cp.async.ca.shared.global [%0], [%1], 16;" :: "r"(s), "l"(g))
#define CP_COMMIT() asm volatile("cp.async.commit_group;" ::: "memory")
#define CP_WAIT0()  asm volatile("cp.async.wait_group 0;" ::: "memory")
#define STS_V2(a, x, y) asm volatile("st.shared.v2.b32 [%0], {%1,%2};" :: "r"(a), "r"(x), "r"(y))

// pack (bf16(x),bf16(y)) and residual pair
__device__ __forceinline__ void split2(float x, float y, u32& hi, u32& lo) {
    __nv_bfloat162 h = __floats2bfloat162_rn(x, y);
    float hx = __bfloat162float(__low2bfloat16(h));
    float hy = __bfloat162float(__high2bfloat16(h));
    __nv_bfloat162 l = __floats2bfloat162_rn(x - hx, y - hy);
    hi = *reinterpret_cast<u32*>(&h);
    lo = *reinterpret_cast<u32*>(&l);
}

// ---------------- monotonic float<->int for atomicMax ----------------------
__device__ __forceinline__ int mono_enc(float f) {
    int i = __float_as_int(f);
    return i >= 0 ? i : (i ^ 0x7FFFFFFF);
}
__device__ __forceinline__ float mono_dec(int i) {
    int j = i >= 0 ? i : (i ^ 0x7FFFFFFF);
    return __int_as_float(j);
}

// ---------------- tiny utility kernels -------------------------------------
__global__ void fill_int(int* p, int v, int n) {
    int i = blockIdx.x * blockDim.x + threadIdx.x;
    if (i < n) p[i] = v;
}

// W[K,Nsrc] -> Wh/Wl[N][K] bf16 split (pad cols Nsrc..N-1 with 0)
__global__ void prep_w(const float* __restrict__ W, __nv_bfloat16* __restrict__ Wh,
                       __nv_bfloat16* __restrict__ Wl, int K, int N, int Nsrc) {
    long long i = (long long)blockIdx.x * 256 + threadIdx.x;
    if (i >= (long long)N * K) return;
    int n = (int)(i / K), k = (int)(i - (long long)n * K);
    float v = (n < Nsrc) ? W[(size_t)k * Nsrc + n] : 0.f;
    __nv_bfloat16 h = __float2bfloat16(v);
    Wh[i] = h;
    Wl[i] = __float2bfloat16(v - __bfloat162float(h));
}

// ---------------- CSR build -------------------------------------------------
__global__ void count_deg(const int* __restrict__ ei, int E, int n,
                          int* degA, int* degL, int* degR) {
    int e = blockIdx.x * blockDim.x + threadIdx.x;
    if (e < E) {
        int s = ei[e], d = ei[E + e];
        atomicAdd(&degA[d], 1);
        atomicAdd(&degL[s], 1);
        atomicAdd(&degR[d], 1);
    } else if (e < E + n) {
        atomicAdd(&degA[e - E], 1);
    }
}

__global__ void scan3_kernel(const int* dA, int* rA, int* cA,
                             const int* dL, int* rL, int* cL,
                             const int* dR, int* rR, int* cR, int n) {
    const int* deg = blockIdx.x == 0 ? dA : (blockIdx.x == 1 ? dL : dR);
    int* rowoff    = blockIdx.x == 0 ? rA : (blockIdx.x == 1 ? rL : rR);
    int* cur       = blockIdx.x == 0 ? cA : (blockIdx.x == 1 ? cL : cR);
    __shared__ int sh[1024];
    __shared__ int carry;
    int tid = threadIdx.x;
    if (tid == 0) carry = 0;
    __syncthreads();
    for (int base = 0; base < n; base += 1024) {
        int i = base + tid;
        int v = (i < n) ? deg[i] : 0;
        sh[tid] = v;
        __syncthreads();
        for (int off = 1; off < 1024; off <<= 1) {
            int t = (tid >= off) ? sh[tid - off] : 0;
            __syncthreads();
            sh[tid] += t;
            __syncthreads();
        }
        int excl = sh[tid] - v + carry;
        if (i < n) { rowoff[i] = excl; cur[i] = excl; }
        __syncthreads();
        if (tid == 1023) carry += sh[1023];
        __syncthreads();
    }
    if (tid == 0) rowoff[n] = carry;
}

__global__ void fill_adj(const int* __restrict__ ei, int E, int n,
                         int* curA, int* adjA, int* curL, int* eidL,
                         int* curR, int* eidR) {
    int e = blockIdx.x * blockDim.x + threadIdx.x;
    if (e < E) {
        int s = ei[e], d = ei[E + e];
        int p = atomicAdd(&curA[d], 1); adjA[p] = s;
        p = atomicAdd(&curL[s], 1); eidL[p] = e;
        p = atomicAdd(&curR[d], 1); eidR[p] = e;
    } else if (e < E + n) {
        int node = e - E;
        int p = atomicAdd(&curA[node], 1); adjA[p] = node;
    }
}

// ---------------- mma.sync GEMM ---------------------------------------------
// C[M,N] = act(A @ W + bias), W given as split-bf16 [N][K] (K-major rows).
// 128x128 CTA tile, 8 warps of 32x64, BK=32 double-buffered, 3-term bf16 split.
// FUSED==1: A row r = relu(decode(xpi[r]) @ We1 + be1), K must be 256.
#define APITCH 40   // bf16 units per smem row (80 bytes, conflict-free ldmatrix)
#define STAGE_BYTES 40960
template<int FUSED>
__global__ __launch_bounds__(256, 1)
void mma_gemm(const float* __restrict__ A,
              const __nv_bfloat16* __restrict__ Bh, const __nv_bfloat16* __restrict__ Bl,
              const float* __restrict__ bias, float* __restrict__ C,
              int M, int N, int K, int Cld, int Nstore, int act,
              const int* __restrict__ xpi,
              const float* __restrict__ We1, const float* __restrict__ be1) {
    extern __shared__ char dsm[];
    __shared__ float xps[128][6];
    const u32 dbase = (smem_u32(dsm) + 127) & ~127u;
    const int tid = threadIdx.x, lane = tid & 31, wid = tid >> 5;
    const int mwarp = wid & 3, nwarp = wid >> 2;
    const int blockRow = blockIdx.y * 128, blockCol = blockIdx.x * 128;

    if constexpr (FUSED) {
        for (int i = tid; i < 128 * 6; i += 256) {
            int m = i / 6, f = i - m * 6;
            int gr = blockRow + m;
            xps[m][f] = (gr < M) ? mono_dec(xpi[(size_t)gr * 6 + f]) : 0.f;
        }
        __syncthreads();
    }

    float acc[2][8][4];
#pragma unroll
    for (int m = 0; m < 2; m++)
#pragma unroll
        for (int n = 0; n < 8; n++)
#pragma unroll
            for (int j = 0; j < 4; j++) acc[m][n][j] = 0.f;

    const int nch = K >> 5;
    float areg[16];

    // ---- helpers as lambdas ----
    auto issueB = [&](int c, int st) {
        int k0 = c << 5;
        u32 sb = dbase + st * STAGE_BYTES;
#pragma unroll
        for (int l = 0; l < 4; l++) {
            int idx = tid + l * 256;
            int arr = idx >> 9, rem = idx & 511, row = rem >> 2, seg = rem & 3;
            const __nv_bfloat16* gsrc =
                (arr ? Bl : Bh) + (size_t)(blockCol + row) * K + k0 + seg * 8;
            u32 sdst = sb + (arr ? 30720 : 20480) + (row * APITCH + seg * 8) * 2;
            CP_ASYNC16(sdst, gsrc);
        }
        CP_COMMIT();
    };
    auto loadA = [&](int c) {
        int k0 = c << 5;
#pragma unroll
        for (int l = 0; l < 4; l++) {
            int idx = tid + l * 256;
            int row = idx >> 3, q = idx & 7;
            int gr = blockRow + row;
            float4 v = make_float4(0.f, 0.f, 0.f, 0.f);
            if (gr < M) v = *(const float4*)(A + (size_t)gr * K + k0 + (q << 2));
            areg[l * 4 + 0] = v.x; areg[l * 4 + 1] = v.y;
            areg[l * 4 + 2] = v.z; areg[l * 4 + 3] = v.w;
        }
    };
    auto storeA = [&](int c, int st) {
        int k0 = c << 5;
        u32 sb = dbase + st * STAGE_BYTES;
#pragma unroll
        for (int l = 0; l < 4; l++) {
            int idx = tid + l * 256;
            int row = idx >> 3, q = idx & 7;
            float v0, v1, v2, v3;
            if constexpr (FUSED) {
                float x0 = xps[row][0], x1 = xps[row][1], x2 = xps[row][2];
                float x3 = xps[row][3], x4 = xps[row][4], x5 = xps[row][5];
                int kb = k0 + (q << 2);
                float vv[4];
#pragma unroll
                for (int j = 0; j < 4; j++) {
                    int kk = kb + j;
                    float t = __ldg(&be1[kk])
                            + x0 * __ldg(&We1[kk])        + x1 * __ldg(&We1[256 + kk])
                            + x2 * __ldg(&We1[512 + kk])  + x3 * __ldg(&We1[768 + kk])
                            + x4 * __ldg(&We1[1024 + kk]) + x5 * __ldg(&We1[1280 + kk]);
                    vv[j] = fmaxf(t, 0.f);
                }
                v0 = vv[0]; v1 = vv[1]; v2 = vv[2]; v3 = vv[3];
            } else {
                v0 = areg[l * 4]; v1 = areg[l * 4 + 1];
                v2 = areg[l * 4 + 2]; v3 = areg[l * 4 + 3];
            }
            u32 h0, l0, h1, l1;
            split2(v0, v1, h0, l0);
            split2(v2, v3, h1, l1);
            u32 so = (row * APITCH + (q << 2)) * 2;
            STS_V2(sb + so, h0, h1);
            STS_V2(sb + 10240 + so, l0, l1);
        }
    };
    auto compute = [&](int st) {
        u32 sb = dbase + st * STAGE_BYTES;
        u32 Ah_ = sb, Al_ = sb + 10240, Bh_ = sb + 20480, Bl_ = sb + 30720;
        int arow = 32 * mwarp + (lane & 15);
        int acol = (lane >> 4) * 8;
        int brow = (lane & 7) + ((lane >> 4) << 3);
        int bcol = ((lane >> 3) & 1) * 8;
#pragma unroll
        for (int ks = 0; ks < 2; ks++) {
            int koff = ks * 16;
            u32 ah[2][4], al[2][4];
#pragma unroll
            for (int m = 0; m < 2; m++) {
                u32 ao = ((arow + m * 16) * APITCH + acol + koff) * 2;
                LDSM4(ah[m], Ah_ + ao);
                LDSM4(al[m], Al_ + ao);
            }
#pragma unroll
            for (int p = 0; p < 4; p++) {
                int n0 = 64 * nwarp + p * 16;
                u32 bo = ((n0 + brow) * APITCH + bcol + koff) * 2;
                u32 bh[4], bl[4];
                LDSM4(bh, Bh_ + bo);
                LDSM4(bl, Bl_ + bo);
#pragma unroll
                for (int m = 0; m < 2; m++) {
                    MMA16816(acc[m][2 * p],     ah[m], bh[0], bh[1]);
                    MMA16816(acc[m][2 * p],     ah[m], bl[0], bl[1]);
                    MMA16816(acc[m][2 * p],     al[m], bh[0], bh[1]);
                    MMA16816(acc[m][2 * p + 1], ah[m], bh[2], bh[3]);
                    MMA16816(acc[m][2 * p + 1], ah[m], bl[2], bl[3]);
                    MMA16816(acc[m][2 * p + 1], al[m], bh[2], bh[3]);
                }
            }
        }
    };

    // ---- prologue: stage 0 ----
    issueB(0, 0);
    if constexpr (!FUSED) loadA(0);
    storeA(0, 0);
    CP_WAIT0();
    __syncthreads();

    int cur = 0;
    for (int c = 0; c < nch; c++) {
        int nxt = cur ^ 1;
        if (c + 1 < nch) {
            issueB(c + 1, nxt);
            if constexpr (!FUSED) loadA(c + 1);
        }
        compute(cur);
        if (c + 1 < nch) {
            storeA(c + 1, nxt);
            CP_WAIT0();
        }
        __syncthreads();
        cur = nxt;
    }

    // ---- epilogue ----
    int g = lane >> 2, t = lane & 3;
#pragma unroll
    for (int m = 0; m < 2; m++) {
        int row0 = blockRow + 32 * mwarp + m * 16 + g;
#pragma unroll
        for (int nt = 0; nt < 8; nt++) {
            int col0 = blockCol + 64 * nwarp + nt * 8 + t * 2;
#pragma unroll
            for (int half = 0; half < 2; half++) {
                int r = row0 + half * 8;
                if (r < M) {
#pragma unroll
                    for (int j = 0; j < 2; j++) {
                        int gc = col0 + j;
                        if (gc < Nstore) {
                            float v = acc[m][nt][half * 2 + j] + (bias ? bias[gc] : 0.f);
                            if (act) v = fmaxf(v, 0.f);
                            C[(size_t)r * Cld + gc] = v;
                        }
                    }
                }
            }
        }
    }
}

// ---------------- GAT attention scalars -------------------------------------
__global__ void sd_kernel(const float* __restrict__ xl, const float* __restrict__ asr,
                          const float* __restrict__ adt, float* __restrict__ s,
                          float* __restrict__ d, int n, int H, int C) {
    int warp = (blockIdx.x * blockDim.x + threadIdx.x) >> 5;
    int lane = threadIdx.x & 31;
    if (warp >= n * H) return;
    int node = warp / H, h = warp - node * H;
    const float* row = xl + (size_t)node * H * C + (size_t)h * C;
    float ss = 0.f, dd = 0.f;
    for (int c = lane; c < C; c += 32) {
        float v = row[c];
        ss += v * asr[h * C + c];
        dd += v * adt[h * C + c];
    }
#pragma unroll
    for (int o = 16; o; o >>= 1) {
        ss += __shfl_down_sync(~0u, ss, o);
        dd += __shfl_down_sync(~0u, dd, o);
    }
    if (!lane) { s[warp] = ss; d[warp] = dd; }
}

// ---------------- GAT aggregation (CSR, atomic-free) ------------------------
template<int H, int C>
__launch_bounds__(256)
__global__ void gat_agg(const int* __restrict__ row, const int* __restrict__ adj,
                        const float* __restrict__ s, const float* __restrict__ dvec,
                        const float* __restrict__ xl, const float* __restrict__ bias,
                        float* __restrict__ out, int ldout, int doElu) {
    constexpr int HC = H * C;
    constexpr int CAP = 512;
    constexpr int PT = (HC + 255) / 256;
    __shared__ float al[CAP * H];
    __shared__ int asrc[CAP];
    __shared__ float mh[8], zinv[8];

    int n = blockIdx.x, tid = threadIdx.x, w = tid >> 5, lane = tid & 31;
    int start = row[n], deg = row[n + 1] - start;

    if (w < H) {
        float dh = dvec[n * H + w];
        float m = -FLT_MAX;
        for (int i = lane; i < deg; i += 32) {
            float a = s[adj[start + i] * H + w] + dh;
            a = a > 0.f ? a : 0.2f * a;
            m = fmaxf(m, a);
        }
#pragma unroll
        for (int o = 16; o; o >>= 1) m = fmaxf(m, __shfl_xor_sync(~0u, m, o));
        float z = 0.f;
        for (int i = lane; i < deg; i += 32) {
            float a = s[adj[start + i] * H + w] + dh;
            a = a > 0.f ? a : 0.2f * a;
            z += expf(a - m);
        }
#pragma unroll
        for (int o = 16; o; o >>= 1) z += __shfl_xor_sync(~0u, z, o);
        if (lane == 0) { mh[w] = m; zinv[w] = 1.f / (z + 1e-16f); }
    }
    __syncthreads();

    float acc[PT];
#pragma unroll
    for (int p = 0; p < PT; p++) {
        int c = tid + p * 256;
        acc[p] = (c < HC) ? bias[c] : 0.f;
    }

    for (int base = 0; base < deg; base += CAP) {
        int cnt = min(CAP, deg - base);
        __syncthreads();
        for (int i = tid; i < cnt; i += 256) asrc[i] = adj[start + base + i];
        __syncthreads();
        for (int i = tid; i < cnt * H; i += 256) {
            int e = i / H, h = i - e * H;
            float a = s[asrc[e] * H + h] + dvec[n * H + h];
            a = a > 0.f ? a : 0.2f * a;
            al[e * H + h] = expf(a - mh[h]) * zinv[h];
        }
        __syncthreads();
#pragma unroll
        for (int p = 0; p < PT; p++) {
            int c = tid + p * 256;
            if (c < HC) {
                int h = c / C;
                float a = acc[p];
                for (int i = 0; i < cnt; i++)
                    a += al[i * H + h] * xl[(size_t)asrc[i] * HC + c];
                acc[p] = a;
            }
        }
    }

#pragma unroll
    for (int p = 0; p < PT; p++) {
        int c = tid + p * 256;
        if (c < HC) {
            float v = acc[p];
            if (doElu) v = v > 0.f ? v : expm1f(v);
            out[(size_t)n * ldout + c] = v;
        }
    }
}

// ---------------- scatter-mean (CSR gather) ---------------------------------
__launch_bounds__(256)
__global__ void mean_gather(const int* __restrict__ row, const int* __restrict__ eid,
                            const float* __restrict__ xp2, float* __restrict__ fin,
                            int off) {
    __shared__ int eids[512];
    int n = blockIdx.x, tid = threadIdx.x;
    int start = row[n], deg = row[n + 1] - start;
    float a0 = 0.f, a1 = 0.f;
    for (int base = 0; base < deg; base += 512) {
        int cnt = min(512, deg - base);
        __syncthreads();
        for (int i = tid; i < cnt; i += 256) eids[i] = eid[start + base + i];
        __syncthreads();
        for (int i = 0; i < cnt; i++) {
            const float* r = xp2 + (size_t)eids[i] * 512;
            a0 += r[tid];
            a1 += r[tid + 256];
        }
    }
    float inv = 1.f / fmaxf((float)deg, 1.f);
    fin[(size_t)n * 1536 + off + tid] = a0 * inv;
    fin[(size_t)n * 1536 + off + tid + 256] = a1 * inv;
}

// ---------------- synapse max-pool ------------------------------------------
__global__ void synapse_max(const float* __restrict__ syn, const int* __restrict__ sidx,
                            int* __restrict__ xpi, int P) {
    int idx = blockIdx.x * blockDim.x + threadIdx.x;
    if (idx >= P * 6) return;
    int p = idx / 6, f = idx - p * 6;
    atomicMax(&xpi[(size_t)sidx[p] * 6 + f], mono_enc(syn[(size_t)p * 6 + f]));
}

// ---------------- host ------------------------------------------------------
static inline int g1(long long total) { return (int)((total + 255) / 256); }
#define GEMM_DSM (2 * STAGE_BYTES + 128)

extern "C" void kernel_launch(void* const* d_in, const int* in_sizes, int n_in,
                              void* d_out, int out_size) {
    const int*   ei   = (const int*)d_in[0];
    const float* syn  = (const float*)d_in[2];
    const int*   sidx = (const int*)d_in[3];
    const float* x_p  = (const float*)d_in[5];
    const float* W1   = (const float*)d_in[6];
    const float* as1  = (const float*)d_in[7];
    const float* ad1  = (const float*)d_in[8];
    const float* b1   = (const float*)d_in[9];
    const float* W2   = (const float*)d_in[10];
    const float* as2  = (const float*)d_in[11];
    const float* ad2  = (const float*)d_in[12];
    const float* b2   = (const float*)d_in[13];
    const float* We1  = (const float*)d_in[14];
    const float* be1  = (const float*)d_in[15];
    const float* We2  = (const float*)d_in[16];
    const float* be2  = (const float*)d_in[17];
    const float* Wc1  = (const float*)d_in[18];
    const float* bc1  = (const float*)d_in[19];
    const float* Wc2  = (const float*)d_in[20];
    const float* bc2  = (const float*)d_in[21];

    const int E = in_sizes[0] / 2;
    const int P = in_sizes[2] / 6;
    const int N = in_sizes[5] / 128;
    const int NCLS = in_sizes[20] / 512;
    float* out = (float*)d_out;

    float *bufA, *bufB, *fin, *hc, *s, *d, *xp2;
    int *xpi, *degA, *degL, *degR, *rowA, *rowL, *rowR, *curA, *curL, *curR,
        *adjA, *eidL, *eidR;
    __nv_bfloat16 *w1h, *w1l, *w2h, *w2l, *we2h, *we2l, *wc1h, *wc1l, *wc2h, *wc2l;
    cudaGetSymbolAddress((void**)&bufA, g_bufA);
    cudaGetSymbolAddress((void**)&bufB, g_bufB);
    cudaGetSymbolAddress((void**)&fin,  g_fin);
    cudaGetSymbolAddress((void**)&hc,   g_hc);
    cudaGetSymbolAddress((void**)&s,    g_s);
    cudaGetSymbolAddress((void**)&d,    g_d);
    cudaGetSymbolAddress((void**)&xpi,  g_xpi);
    cudaGetSymbolAddress((void**)&xp2,  g_xp2);
    cudaGetSymbolAddress((void**)&degA, g_degA);
    cudaGetSymbolAddress((void**)&degL, g_degL);
    cudaGetSymbolAddress((void**)&degR, g_degR);
    cudaGetSymbolAddress((void**)&rowA, g_rowA);
    cudaGetSymbolAddress((void**)&rowL, g_rowL);
    cudaGetSymbolAddress((void**)&rowR, g_rowR);
    cudaGetSymbolAddress((void**)&curA, g_curA);
    cudaGetSymbolAddress((void**)&curL, g_curL);
    cudaGetSymbolAddress((void**)&curR, g_curR);
    cudaGetSymbolAddress((void**)&adjA, g_adjA);
    cudaGetSymbolAddress((void**)&eidL, g_eidL);
    cudaGetSymbolAddress((void**)&eidR, g_eidR);
    cudaGetSymbolAddress((void**)&w1h, g_w1h);  cudaGetSymbolAddress((void**)&w1l, g_w1l);
    cudaGetSymbolAddress((void**)&w2h, g_w2h);  cudaGetSymbolAddress((void**)&w2l, g_w2l);
    cudaGetSymbolAddress((void**)&we2h, g_we2h); cudaGetSymbolAddress((void**)&we2l, g_we2l);
    cudaGetSymbolAddress((void**)&wc1h, g_wc1h); cudaGetSymbolAddress((void**)&wc1l, g_wc1l);
    cudaGetSymbolAddress((void**)&wc2h, g_wc2h); cudaGetSymbolAddress((void**)&wc2l, g_wc2l);

    cudaFuncSetAttribute(mma_gemm<0>, cudaFuncAttributeMaxDynamicSharedMemorySize, GEMM_DSM);
    cudaFuncSetAttribute(mma_gemm<1>, cudaFuncAttributeMaxDynamicSharedMemorySize, GEMM_DSM);

    // ===== weight prep (bf16 split + transpose) =====
    prep_w<<<g1(512LL * 128), 256>>>(W1, w1h, w1l, 128, 512, 512);
    prep_w<<<g1(512LL * 512), 256>>>(W2, w2h, w2l, 512, 512, 512);
    prep_w<<<g1(512LL * 256), 256>>>(We2, we2h, we2l, 256, 512, 512);
    prep_w<<<g1(512LL * 1536), 256>>>(Wc1, wc1h, wc1l, 1536, 512, 512);
    prep_w<<<g1(256LL * 512), 256>>>(Wc2, wc2h, wc2l, 512, 256, NCLS);

    // ===== CSR build =====
    fill_int<<<g1(N), 256>>>(degA, 0, N);
    fill_int<<<g1(N), 256>>>(degL, 0, N);
    fill_int<<<g1(N), 256>>>(degR, 0, N);
    count_deg<<<g1(E + N), 256>>>(ei, E, N, degA, degL, degR);
    scan3_kernel<<<3, 1024>>>(degA, rowA, curA, degL, rowL, curL, degR, rowR, curR, N);
    fill_adj<<<g1(E + N), 256>>>(ei, E, N, curA, adjA, curL, eidL, curR, eidR);

    // ===== synapse branch =====
    fill_int<<<g1((long long)E * 6), 256>>>(xpi, 0x80800000, E * 6);
    synapse_max<<<g1((long long)P * 6), 256>>>(syn, sidx, xpi, P);
    {
        dim3 g(4, (E + 127) / 128);
        mma_gemm<1><<<g, 256, GEMM_DSM>>>(nullptr, we2h, we2l, be2, xp2,
                                          E, 512, 256, 512, 512, 0, xpi, We1, be1);
    }

    // ===== GAT layer 1 =====
    {
        dim3 g(4, (N + 127) / 128);
        mma_gemm<0><<<g, 256, GEMM_DSM>>>(x_p, w1h, w1l, nullptr, bufA,
                                          N, 512, 128, 512, 512, 0, nullptr, nullptr, nullptr);
    }
    sd_kernel<<<g1((long long)N * 8 * 32), 256>>>(bufA, as1, ad1, s, d, N, 8, 64);
    gat_agg<8, 64><<<N, 256>>>(rowA, adjA, s, d, bufA, b1, bufB, 512, 1);

    // ===== GAT layer 2 =====
    {
        dim3 g(4, (N + 127) / 128);
        mma_gemm<0><<<g, 256, GEMM_DSM>>>(bufB, w2h, w2l, nullptr, bufA,
                                          N, 512, 512, 512, 512, 0, nullptr, nullptr, nullptr);
    }
    sd_kernel<<<g1((long long)N * 32), 256>>>(bufA, as2, ad2, s, d, N, 1, 512);
    gat_agg<1, 512><<<N, 256>>>(rowA, adjA, s, d, bufA, b2, fin, 1536, 0);

    // ===== scatter means into fin[:,512:1536] =====
    mean_gather<<<N, 256>>>(rowL, eidL, xp2, fin, 512);
    mean_gather<<<N, 256>>>(rowR, eidR, xp2, fin, 1024);

    // ===== classifier =====
    {
        dim3 g(4, (N + 127) / 128);
        mma_gemm<0><<<g, 256, GEMM_DSM>>>(fin, wc1h, wc1l, bc1, hc,
                                          N, 512, 1536, 512, 512, 1, nullptr, nullptr, nullptr);
    }
    {
        dim3 g(2, (N + 127) / 128);
        mma_gemm<0><<<g, 256, GEMM_DSM>>>(hc, wc2h, wc2l, bc2, out,
                                          N, 256, 512, NCLS, NCLS, 0, nullptr, nullptr, nullptr);
    }
}

// round 8
// speedup vs baseline: 5.3658x; 1.1242x over previous
#include <cuda_runtime.h>
#include <cuda_bf16.h>
#include <math.h>
#include <float.h>

#define NMAX 20000
#define EMAX 200000

typedef unsigned long long ull;
typedef unsigned int u32;
typedef __nv_bfloat16 bf16;

// ---------------- scratch (device globals; no allocation allowed) ----------
__device__ float g_bufA[NMAX * 512];          // xl (fp32, GEMM out for GAT layers)
__device__ float g_s[NMAX * 8];
__device__ float g_d[NMAX * 8];
__device__ int   g_xpi[EMAX * 6];
__device__ float g_xp2[EMAX * 512];
__device__ int g_degA[NMAX], g_degL[NMAX], g_degR[NMAX];
__device__ int g_rowA[NMAX + 1], g_rowL[NMAX + 1], g_rowR[NMAX + 1];
__device__ int g_curA[NMAX], g_curL[NMAX], g_curR[NMAX];
__device__ int g_adjA[EMAX + NMAX];
__device__ int g_eidL[EMAX], g_eidR[EMAX];
// split activation pairs (bf16 hi/lo)
__device__ bf16 g_xph[NMAX * 128],  g_xpl[NMAX * 128];
__device__ bf16 g_h1h[EMAX * 256],  g_h1l[EMAX * 256];
__device__ bf16 g_x1h[NMAX * 512],  g_x1l[NMAX * 512];
__device__ bf16 g_finh[NMAX * 1536], g_finl[NMAX * 1536];
__device__ bf16 g_hch[NMAX * 512],  g_hcl[NMAX * 512];
// bf16 split weights, transposed to [N][K]
__device__ bf16 g_w1h[512 * 128],  g_w1l[512 * 128];
__device__ bf16 g_w2h[512 * 512],  g_w2l[512 * 512];
__device__ bf16 g_we2h[512 * 256], g_we2l[512 * 256];
__device__ bf16 g_wc1h[512 * 1536], g_wc1l[512 * 1536];
__device__ bf16 g_wc2h[256 * 512], g_wc2l[256 * 512];

// ---------------- PTX helpers (baseline ISA only) ----------------------------
__device__ __forceinline__ u32 smem_u32(const void* p) {
    u32 a;
    asm("{ .reg .u64 t; cvta.to.shared.u64 t, %1; cvt.u32.u64 %0, t; }" : "=r"(a) : "l"(p));
    return a;
}
#define LDSM4(r, addr) \
    asm volatile("ldmatrix.sync.aligned.m8n8.x4.shared.b16 {%0,%1,%2,%3}, [%4];" \
        : "=r"((r)[0]), "=r"((r)[1]), "=r"((r)[2]), "=r"((r)[3]) : "r"(addr))
#define MMA16816(c, a, b0, b1) \
    asm volatile("mma.sync.aligned.m16n8k16.row.col.f32.bf16.bf16.f32 " \
        "{%0,%1,%2,%3}, {%4,%5,%6,%7}, {%8,%9}, {%0,%1,%2,%3};" \
        : "+f"((c)[0]), "+f"((c)[1]), "+f"((c)[2]), "+f"((c)[3]) \
        : "r"((a)[0]), "r"((a)[1]), "r"((a)[2]), "r"((a)[3]), "r"(b0), "r"(b1))
#define CP_ASYNC16(s, g) \
    asm volatile("cp.async.ca.shared.global [%0], [%1], 16;" :: "r"(s), "l"(g))
#define CP_ASYNC16Z(s, g, sz) \
    asm volatile("cp.async.ca.shared.global [%0], [%1], 16, %2;" :: "r"(s), "l"(g), "r"(sz))
#define CP_COMMIT() asm volatile("cp.async.commit_group;" ::: "memory")
#define CP_WAIT0()  asm volatile("cp.async.wait_group 0;" ::: "memory")
#define CP_WAIT1()  asm volatile("cp.async.wait_group 1;" ::: "memory")

// pack (bf16(x),bf16(y)) and residual pair
__device__ __forceinline__ void split2(float x, float y, u32& hi, u32& lo) {
    __nv_bfloat162 h = __floats2bfloat162_rn(x, y);
    float hx = __bfloat162float(__low2bfloat16(h));
    float hy = __bfloat162float(__high2bfloat16(h));
    __nv_bfloat162 l = __floats2bfloat162_rn(x - hx, y - hy);
    hi = *reinterpret_cast<u32*>(&h);
    lo = *reinterpret_cast<u32*>(&l);
}
__device__ __forceinline__ void split1(float v, bf16& h, bf16& l) {
    h = __float2bfloat16(v);
    l = __float2bfloat16(v - __bfloat162float(h));
}

// ---------------- monotonic float<->int for atomicMax ----------------------
__device__ __forceinline__ int mono_enc(float f) {
    int i = __float_as_int(f);
    return i >= 0 ? i : (i ^ 0x7FFFFFFF);
}
__device__ __forceinline__ float mono_dec(int i) {
    int j = i >= 0 ? i : (i ^ 0x7FFFFFFF);
    return __int_as_float(j);
}

// ---------------- tiny utility kernels -------------------------------------
__global__ void fill_int(int* p, int v, int n) {
    int i = blockIdx.x * blockDim.x + threadIdx.x;
    if (i < n) p[i] = v;
}

// W[K,Nsrc] -> Wh/Wl[N][K] bf16 split (pad cols Nsrc..N-1 with 0)
__global__ void prep_w(const float* __restrict__ W, bf16* __restrict__ Wh,
                       bf16* __restrict__ Wl, int K, int N, int Nsrc) {
    long long i = (long long)blockIdx.x * 256 + threadIdx.x;
    if (i >= (long long)N * K) return;
    int n = (int)(i / K), k = (int)(i - (long long)n * K);
    float v = (n < Nsrc) ? W[(size_t)k * Nsrc + n] : 0.f;
    bf16 h, l;
    split1(v, h, l);
    Wh[i] = h; Wl[i] = l;
}

// X fp32 -> (Xh, Xl) split, 2 elements per thread
__global__ void split_f32(const float* __restrict__ X, bf16* __restrict__ Xh,
                          bf16* __restrict__ Xl, long long n) {
    long long i = ((long long)blockIdx.x * 256 + threadIdx.x) * 2;
    if (i >= n) return;
    u32 h, l;
    split2(X[i], X[i + 1], h, l);
    *(u32*)(Xh + i) = h;
    *(u32*)(Xl + i) = l;
}

// h1 = relu(decode(xpi) @ We1 + be1), written as split bf16 pair. 2 cols/thread.
__global__ void mlp1_split(const int* __restrict__ xpi, const float* __restrict__ We1,
                           const float* __restrict__ be1, bf16* __restrict__ h1h,
                           bf16* __restrict__ h1l, int E) {
    long long idx = (long long)blockIdx.x * 256 + threadIdx.x;
    if (idx >= (long long)E * 128) return;
    int r = (int)(idx >> 7), c2 = ((int)idx & 127) << 1;
    float x0 = mono_dec(__ldg(&xpi[r * 6 + 0]));
    float x1 = mono_dec(__ldg(&xpi[r * 6 + 1]));
    float x2 = mono_dec(__ldg(&xpi[r * 6 + 2]));
    float x3 = mono_dec(__ldg(&xpi[r * 6 + 3]));
    float x4 = mono_dec(__ldg(&xpi[r * 6 + 4]));
    float x5 = mono_dec(__ldg(&xpi[r * 6 + 5]));
    float v[2];
#pragma unroll
    for (int j = 0; j < 2; j++) {
        int kk = c2 + j;
        float t = __ldg(&be1[kk])
                + x0 * __ldg(&We1[kk])        + x1 * __ldg(&We1[256 + kk])
                + x2 * __ldg(&We1[512 + kk])  + x3 * __ldg(&We1[768 + kk])
                + x4 * __ldg(&We1[1024 + kk]) + x5 * __ldg(&We1[1280 + kk]);
        v[j] = fmaxf(t, 0.f);
    }
    u32 h, l;
    split2(v[0], v[1], h, l);
    *(u32*)(h1h + (size_t)r * 256 + c2) = h;
    *(u32*)(h1l + (size_t)r * 256 + c2) = l;
}

// ---------------- CSR build -------------------------------------------------
__global__ void count_deg(const int* __restrict__ ei, int E, int n,
                          int* degA, int* degL, int* degR) {
    int e = blockIdx.x * blockDim.x + threadIdx.x;
    if (e < E) {
        int s = ei[e], d = ei[E + e];
        atomicAdd(&degA[d], 1);
        atomicAdd(&degL[s], 1);
        atomicAdd(&degR[d], 1);
    } else if (e < E + n) {
        atomicAdd(&degA[e - E], 1);
    }
}

__global__ void scan3_kernel(const int* dA, int* rA, int* cA,
                             const int* dL, int* rL, int* cL,
                             const int* dR, int* rR, int* cR, int n) {
    const int* deg = blockIdx.x == 0 ? dA : (blockIdx.x == 1 ? dL : dR);
    int* rowoff    = blockIdx.x == 0 ? rA : (blockIdx.x == 1 ? rL : rR);
    int* cur       = blockIdx.x == 0 ? cA : (blockIdx.x == 1 ? cL : cR);
    __shared__ int sh[1024];
    __shared__ int carry;
    int tid = threadIdx.x;
    if (tid == 0) carry = 0;
    __syncthreads();
    for (int base = 0; base < n; base += 1024) {
        int i = base + tid;
        int v = (i < n) ? deg[i] : 0;
        sh[tid] = v;
        __syncthreads();
        for (int off = 1; off < 1024; off <<= 1) {
            int t = (tid >= off) ? sh[tid - off] : 0;
            __syncthreads();
            sh[tid] += t;
            __syncthreads();
        }
        int excl = sh[tid] - v + carry;
        if (i < n) { rowoff[i] = excl; cur[i] = excl; }
        __syncthreads();
        if (tid == 1023) carry += sh[1023];
        __syncthreads();
    }
    if (tid == 0) rowoff[n] = carry;
}

__global__ void fill_adj(const int* __restrict__ ei, int E, int n,
                         int* curA, int* adjA, int* curL, int* eidL,
                         int* curR, int* eidR) {
    int e = blockIdx.x * blockDim.x + threadIdx.x;
    if (e < E) {
        int s = ei[e], d = ei[E + e];
        int p = atomicAdd(&curA[d], 1); adjA[p] = s;
        p = atomicAdd(&curL[s], 1); eidL[p] = e;
        p = atomicAdd(&curR[d], 1); eidR[p] = e;
    } else if (e < E + n) {
        int node = e - E;
        int p = atomicAdd(&curA[node], 1); adjA[p] = node;
    }
}

// ---------------- mma.sync GEMM (pure cp.async, pre-split operands) ---------
// C[M,N] = act(A @ W + bias); A given as split pair [M][K], W as split [N][K].
// 128x128 CTA tile, 8 warps of 32x64, BK=32 double-buffered, 3-term bf16 split.
// OUT_SPLIT==1: write (Ch, Cl) split bf16 instead of fp32 C (N must be full tiles).
#define APITCH 40
#define STAGE_BYTES 40960
template<int OUT_SPLIT>
__global__ __launch_bounds__(256, 2)
void mma_gemm(const bf16* __restrict__ Ah, const bf16* __restrict__ Al,
              const bf16* __restrict__ Bh, const bf16* __restrict__ Bl,
              const float* __restrict__ bias, float* __restrict__ C,
              bf16* __restrict__ Ch, bf16* __restrict__ Cl,
              int M, int N, int K, int Cld, int Nstore, int act) {
    extern __shared__ char dsm[];
    const u32 dbase = (smem_u32(dsm) + 127) & ~127u;
    const int tid = threadIdx.x, lane = tid & 31, wid = tid >> 5;
    const int mwarp = wid & 3, nwarp = wid >> 2;
    const int blockRow = blockIdx.y * 128, blockCol = blockIdx.x * 128;

    float acc[2][8][4];
#pragma unroll
    for (int m = 0; m < 2; m++)
#pragma unroll
        for (int n = 0; n < 8; n++)
#pragma unroll
            for (int j = 0; j < 4; j++) acc[m][n][j] = 0.f;

    const int nch = K >> 5;

    auto issue = [&](int c, int st) {
        int k0 = c << 5;
        u32 sb = dbase + st * STAGE_BYTES;
        // A hi/lo (rows may exceed M -> zfill)
#pragma unroll
        for (int l = 0; l < 4; l++) {
            int idx = tid + l * 256;
            int arr = idx >> 9, rem = idx & 511, row = rem >> 2, seg = rem & 3;
            int gr = blockRow + row;
            u32 sz = 16;
            if (gr >= M) { gr = 0; sz = 0; }
            const bf16* gsrc = (arr ? Al : Ah) + (size_t)gr * K + k0 + seg * 8;
            u32 sdst = sb + arr * 10240 + (row * APITCH + seg * 8) * 2;
            CP_ASYNC16Z(sdst, gsrc, sz);
        }
        // B hi/lo (always in-bounds)
#pragma unroll
        for (int l = 0; l < 4; l++) {
            int idx = tid + l * 256;
            int arr = idx >> 9, rem = idx & 511, row = rem >> 2, seg = rem & 3;
            const bf16* gsrc = (arr ? Bl : Bh) + (size_t)(blockCol + row) * K + k0 + seg * 8;
            u32 sdst = sb + (arr ? 30720 : 20480) + (row * APITCH + seg * 8) * 2;
            CP_ASYNC16(sdst, gsrc);
        }
        CP_COMMIT();
    };
    auto compute = [&](int st) {
        u32 sb = dbase + st * STAGE_BYTES;
        u32 Ah_ = sb, Al_ = sb + 10240, Bh_ = sb + 20480, Bl_ = sb + 30720;
        int arow = 32 * mwarp + (lane & 15);
        int acol = (lane >> 4) * 8;
        int brow = (lane & 7) + ((lane >> 4) << 3);
        int bcol = ((lane >> 3) & 1) * 8;
#pragma unroll
        for (int ks = 0; ks < 2; ks++) {
            int koff = ks * 16;
            u32 ah[2][4], al[2][4];
#pragma unroll
            for (int m = 0; m < 2; m++) {
                u32 ao = ((arow + m * 16) * APITCH + acol + koff) * 2;
                LDSM4(ah[m], Ah_ + ao);
                LDSM4(al[m], Al_ + ao);
            }
#pragma unroll
            for (int p = 0; p < 4; p++) {
                int n0 = 64 * nwarp + p * 16;
                u32 bo = ((n0 + brow) * APITCH + bcol + koff) * 2;
                u32 bh[4], bl[4];
                LDSM4(bh, Bh_ + bo);
                LDSM4(bl, Bl_ + bo);
#pragma unroll
                for (int m = 0; m < 2; m++) {
                    MMA16816(acc[m][2 * p],     ah[m], bh[0], bh[1]);
                    MMA16816(acc[m][2 * p],     ah[m], bl[0], bl[1]);
                    MMA16816(acc[m][2 * p],     al[m], bh[0], bh[1]);
                    MMA16816(acc[m][2 * p + 1], ah[m], bh[2], bh[3]);
                    MMA16816(acc[m][2 * p + 1], ah[m], bl[2], bl[3]);
                    MMA16816(acc[m][2 * p + 1], al[m], bh[2], bh[3]);
                }
            }
        }
    };

    issue(0, 0);
    int cur = 0;
    for (int c = 0; c < nch; c++) {
        if (c + 1 < nch) {
            issue(c + 1, cur ^ 1);
            CP_WAIT1();
        } else {
            CP_WAIT0();
        }
        __syncthreads();
        compute(cur);
        __syncthreads();
        cur ^= 1;
    }

    // ---- epilogue ----
    int g = lane >> 2, t = lane & 3;
#pragma unroll
    for (int m = 0; m < 2; m++) {
        int row0 = blockRow + 32 * mwarp + m * 16 + g;
#pragma unroll
        for (int nt = 0; nt < 8; nt++) {
            int col0 = blockCol + 64 * nwarp + nt * 8 + t * 2;
#pragma unroll
            for (int half = 0; half < 2; half++) {
                int r = row0 + half * 8;
                if (r >= M) continue;
                float v0 = acc[m][nt][half * 2 + 0];
                float v1 = acc[m][nt][half * 2 + 1];
                if (bias) { v0 += bias[col0]; v1 += bias[col0 + 1]; }
                if (act) { v0 = fmaxf(v0, 0.f); v1 = fmaxf(v1, 0.f); }
                if constexpr (OUT_SPLIT) {
                    u32 h, l;
                    split2(v0, v1, h, l);
                    *(u32*)(Ch + (size_t)r * Cld + col0) = h;
                    *(u32*)(Cl + (size_t)r * Cld + col0) = l;
                } else {
                    if (col0 < Nstore)     C[(size_t)r * Cld + col0] = v0;
                    if (col0 + 1 < Nstore) C[(size_t)r * Cld + col0 + 1] = v1;
                }
            }
        }
    }
}

// ---------------- GAT attention scalars -------------------------------------
__global__ void sd_kernel(const float* __restrict__ xl, const float* __restrict__ asr,
                          const float* __restrict__ adt, float* __restrict__ s,
                          float* __restrict__ d, int n, int H, int C) {
    int warp = (blockIdx.x * blockDim.x + threadIdx.x) >> 5;
    int lane = threadIdx.x & 31;
    if (warp >= n * H) return;
    int node = warp / H, h = warp - node * H;
    const float* row = xl + (size_t)node * H * C + (size_t)h * C;
    float ss = 0.f, dd = 0.f;
    for (int c = lane; c < C; c += 32) {
        float v = row[c];
        ss += v * asr[h * C + c];
        dd += v * adt[h * C + c];
    }
#pragma unroll
    for (int o = 16; o; o >>= 1) {
        ss += __shfl_down_sync(~0u, ss, o);
        dd += __shfl_down_sync(~0u, dd, o);
    }
    if (!lane) { s[warp] = ss; d[warp] = dd; }
}

// ---------------- GAT aggregation (CSR, atomic-free, split bf16 output) -----
template<int H, int C>
__launch_bounds__(256)
__global__ void gat_agg(const int* __restrict__ row, const int* __restrict__ adj,
                        const float* __restrict__ s, const float* __restrict__ dvec,
                        const float* __restrict__ xl, const float* __restrict__ bias,
                        bf16* __restrict__ outh, bf16* __restrict__ outl,
                        int ldout, int doElu) {
    constexpr int HC = H * C;
    constexpr int CAP = 512;
    constexpr int PT = (HC + 255) / 256;
    __shared__ float al[CAP * H];
    __shared__ int asrc[CAP];
    __shared__ float mh[8], zinv[8];

    int n = blockIdx.x, tid = threadIdx.x, w = tid >> 5, lane = tid & 31;
    int start = row[n], deg = row[n + 1] - start;

    if (w < H) {
        float dh = dvec[n * H + w];
        float m = -FLT_MAX;
        for (int i = lane; i < deg; i += 32) {
            float a = s[adj[start + i] * H + w] + dh;
            a = a > 0.f ? a : 0.2f * a;
            m = fmaxf(m, a);
        }
#pragma unroll
        for (int o = 16; o; o >>= 1) m = fmaxf(m, __shfl_xor_sync(~0u, m, o));
        float z = 0.f;
        for (int i = lane; i < deg; i += 32) {
            float a = s[adj[start + i] * H + w] + dh;
            a = a > 0.f ? a : 0.2f * a;
            z += expf(a - m);
        }
#pragma unroll
        for (int o = 16; o; o >>= 1) z += __shfl_xor_sync(~0u, z, o);
        if (lane == 0) { mh[w] = m; zinv[w] = 1.f / (z + 1e-16f); }
    }
    __syncthreads();

    float acc[PT];
#pragma unroll
    for (int p = 0; p < PT; p++) {
        int c = tid + p * 256;
        acc[p] = (c < HC) ? bias[c] : 0.f;
    }

    for (int base = 0; base < deg; base += CAP) {
        int cnt = min(CAP, deg - base);
        __syncthreads();
        for (int i = tid; i < cnt; i += 256) asrc[i] = adj[start + base + i];
        __syncthreads();
        for (int i = tid; i < cnt * H; i += 256) {
            int e = i / H, h = i - e * H;
            float a = s[asrc[e] * H + h] + dvec[n * H + h];
            a = a > 0.f ? a : 0.2f * a;
            al[e * H + h] = expf(a - mh[h]) * zinv[h];
        }
        __syncthreads();
#pragma unroll
        for (int p = 0; p < PT; p++) {
            int c = tid + p * 256;
            if (c < HC) {
                int h = c / C;
                float a = acc[p];
                for (int i = 0; i < cnt; i++)
                    a += al[i * H + h] * xl[(size_t)asrc[i] * HC + c];
                acc[p] = a;
            }
        }
    }

#pragma unroll
    for (int p = 0; p < PT; p++) {
        int c = tid + p * 256;
        if (c < HC) {
            float v = acc[p];
            if (doElu) v = v > 0.f ? v : expm1f(v);
            bf16 h, l;
            split1(v, h, l);
            outh[(size_t)n * ldout + c] = h;
            outl[(size_t)n * ldout + c] = l;
        }
    }
}

// ---------------- scatter-mean (CSR gather, split bf16 output) ---------------
__launch_bounds__(256)
__global__ void mean_gather(const int* __restrict__ row, const int* __restrict__ eid,
                            const float* __restrict__ xp2, bf16* __restrict__ finh,
                            bf16* __restrict__ finl, int off) {
    __shared__ int eids[512];
    int n = blockIdx.x, tid = threadIdx.x;
    int start = row[n], deg = row[n + 1] - start;
    float a0 = 0.f, a1 = 0.f;
    for (int base = 0; base < deg; base += 512) {
        int cnt = min(512, deg - base);
        __syncthreads();
        for (int i = tid; i < cnt; i += 256) eids[i] = eid[start + base + i];
        __syncthreads();
        for (int i = 0; i < cnt; i++) {
            const float* r = xp2 + (size_t)eids[i] * 512;
            a0 += r[tid];
            a1 += r[tid + 256];
        }
    }
    float inv = 1.f / fmaxf((float)deg, 1.f);
    a0 *= inv; a1 *= inv;
    bf16 h, l;
    split1(a0, h, l);
    finh[(size_t)n * 1536 + off + tid] = h;
    finl[(size_t)n * 1536 + off + tid] = l;
    split1(a1, h, l);
    finh[(size_t)n * 1536 + off + tid + 256] = h;
    finl[(size_t)n * 1536 + off + tid + 256] = l;
}

// ---------------- synapse max-pool ------------------------------------------
__global__ void synapse_max(const float* __restrict__ syn, const int* __restrict__ sidx,
                            int* __restrict__ xpi, int P) {
    int idx = blockIdx.x * blockDim.x + threadIdx.x;
    if (idx >= P * 6) return;
    int p = idx / 6, f = idx - p * 6;
    atomicMax(&xpi[(size_t)sidx[p] * 6 + f], mono_enc(syn[(size_t)p * 6 + f]));
}

// ---------------- host ------------------------------------------------------
static inline int g1(long long total) { return (int)((total + 255) / 256); }
#define GEMM_DSM (2 * STAGE_BYTES + 128)

extern "C" void kernel_launch(void* const* d_in, const int* in_sizes, int n_in,
                              void* d_out, int out_size) {
    const int*   ei   = (const int*)d_in[0];
    const float* syn  = (const float*)d_in[2];
    const int*   sidx = (const int*)d_in[3];
    const float* x_p  = (const float*)d_in[5];
    const float* W1   = (const float*)d_in[6];
    const float* as1  = (const float*)d_in[7];
    const float* ad1  = (const float*)d_in[8];
    const float* b1   = (const float*)d_in[9];
    const float* W2   = (const float*)d_in[10];
    const float* as2  = (const float*)d_in[11];
    const float* ad2  = (const float*)d_in[12];
    const float* b2   = (const float*)d_in[13];
    const float* We1  = (const float*)d_in[14];
    const float* be1  = (const float*)d_in[15];
    const float* We2  = (const float*)d_in[16];
    const float* be2  = (const float*)d_in[17];
    const float* Wc1  = (const float*)d_in[18];
    const float* bc1  = (const float*)d_in[19];
    const float* Wc2  = (const float*)d_in[20];
    const float* bc2  = (const float*)d_in[21];

    const int E = in_sizes[0] / 2;
    const int P = in_sizes[2] / 6;
    const int N = in_sizes[5] / 128;
    const int NCLS = in_sizes[20] / 512;
    float* out = (float*)d_out;

    float *bufA, *s, *d, *xp2;
    int *xpi, *degA, *degL, *degR, *rowA, *rowL, *rowR, *curA, *curL, *curR,
        *adjA, *eidL, *eidR;
    bf16 *xph, *xpl, *h1h, *h1l, *x1h, *x1l, *finh, *finl, *hch, *hcl;
    bf16 *w1h, *w1l, *w2h, *w2l, *we2h, *we2l, *wc1h, *wc1l, *wc2h, *wc2l;
    cudaGetSymbolAddress((void**)&bufA, g_bufA);
    cudaGetSymbolAddress((void**)&s,    g_s);
    cudaGetSymbolAddress((void**)&d,    g_d);
    cudaGetSymbolAddress((void**)&xpi,  g_xpi);
    cudaGetSymbolAddress((void**)&xp2,  g_xp2);
    cudaGetSymbolAddress((void**)&degA, g_degA);
    cudaGetSymbolAddress((void**)&degL, g_degL);
    cudaGetSymbolAddress((void**)&degR, g_degR);
    cudaGetSymbolAddress((void**)&rowA, g_rowA);
    cudaGetSymbolAddress((void**)&rowL, g_rowL);
    cudaGetSymbolAddress((void**)&rowR, g_rowR);
    cudaGetSymbolAddress((void**)&curA, g_curA);
    cudaGetSymbolAddress((void**)&curL, g_curL);
    cudaGetSymbolAddress((void**)&curR, g_curR);
    cudaGetSymbolAddress((void**)&adjA, g_adjA);
    cudaGetSymbolAddress((void**)&eidL, g_eidL);
    cudaGetSymbolAddress((void**)&eidR, g_eidR);
    cudaGetSymbolAddress((void**)&xph, g_xph);  cudaGetSymbolAddress((void**)&xpl, g_xpl);
    cudaGetSymbolAddress((void**)&h1h, g_h1h);  cudaGetSymbolAddress((void**)&h1l, g_h1l);
    cudaGetSymbolAddress((void**)&x1h, g_x1h);  cudaGetSymbolAddress((void**)&x1l, g_x1l);
    cudaGetSymbolAddress((void**)&finh, g_finh); cudaGetSymbolAddress((void**)&finl, g_finl);
    cudaGetSymbolAddress((void**)&hch, g_hch);  cudaGetSymbolAddress((void**)&hcl, g_hcl);
    cudaGetSymbolAddress((void**)&w1h, g_w1h);  cudaGetSymbolAddress((void**)&w1l, g_w1l);
    cudaGetSymbolAddress((void**)&w2h, g_w2h);  cudaGetSymbolAddress((void**)&w2l, g_w2l);
    cudaGetSymbolAddress((void**)&we2h, g_we2h); cudaGetSymbolAddress((void**)&we2l, g_we2l);
    cudaGetSymbolAddress((void**)&wc1h, g_wc1h); cudaGetSymbolAddress((void**)&wc1l, g_wc1l);
    cudaGetSymbolAddress((void**)&wc2h, g_wc2h); cudaGetSymbolAddress((void**)&wc2l, g_wc2l);

    cudaFuncSetAttribute(mma_gemm<0>, cudaFuncAttributeMaxDynamicSharedMemorySize, GEMM_DSM);
    cudaFuncSetAttribute(mma_gemm<1>, cudaFuncAttributeMaxDynamicSharedMemorySize, GEMM_DSM);

    // ===== weight prep (bf16 split + transpose) =====
    prep_w<<<g1(512LL * 128), 256>>>(W1, w1h, w1l, 128, 512, 512);
    prep_w<<<g1(512LL * 512), 256>>>(W2, w2h, w2l, 512, 512, 512);
    prep_w<<<g1(512LL * 256), 256>>>(We2, we2h, we2l, 256, 512, 512);
    prep_w<<<g1(512LL * 1536), 256>>>(Wc1, wc1h, wc1l, 1536, 512, 512);
    prep_w<<<g1(256LL * 512), 256>>>(Wc2, wc2h, wc2l, 512, 256, NCLS);
    split_f32<<<g1((long long)N * 64), 256>>>(x_p, xph, xpl, (long long)N * 128);

    // ===== CSR build =====
    fill_int<<<g1(N), 256>>>(degA, 0, N);
    fill_int<<<g1(N), 256>>>(degL, 0, N);
    fill_int<<<g1(N), 256>>>(degR, 0, N);
    count_deg<<<g1(E + N), 256>>>(ei, E, N, degA, degL, degR);
    scan3_kernel<<<3, 1024>>>(degA, rowA, curA, degL, rowL, curL, degR, rowR, curR, N);
    fill_adj<<<g1(E + N), 256>>>(ei, E, N, curA, adjA, curL, eidL, curR, eidR);

    // ===== synapse branch =====
    fill_int<<<g1((long long)E * 6), 256>>>(xpi, 0x80800000, E * 6);
    synapse_max<<<g1((long long)P * 6), 256>>>(syn, sidx, xpi, P);
    mlp1_split<<<g1((long long)E * 128), 256>>>(xpi, We1, be1, h1h, h1l, E);
    {
        dim3 g(4, (E + 127) / 128);
        mma_gemm<0><<<g, 256, GEMM_DSM>>>(h1h, h1l, we2h, we2l, be2, xp2,
                                          nullptr, nullptr, E, 512, 256, 512, 512, 0);
    }

    // ===== GAT layer 1 =====
    {
        dim3 g(4, (N + 127) / 128);
        mma_gemm<0><<<g, 256, GEMM_DSM>>>(xph, xpl, w1h, w1l, nullptr, bufA,
                                          nullptr, nullptr, N, 512, 128, 512, 512, 0);
    }
    sd_kernel<<<g1((long long)N * 8 * 32), 256>>>(bufA, as1, ad1, s, d, N, 8, 64);
    gat_agg<8, 64><<<N, 256>>>(rowA, adjA, s, d, bufA, b1, x1h, x1l, 512, 1);

    // ===== GAT layer 2 =====
    {
        dim3 g(4, (N + 127) / 128);
        mma_gemm<0><<<g, 256, GEMM_DSM>>>(x1h, x1l, w2h, w2l, nullptr, bufA,
                                          nullptr, nullptr, N, 512, 512, 512, 512, 0);
    }
    sd_kernel<<<g1((long long)N * 32), 256>>>(bufA, as2, ad2, s, d, N, 1, 512);
    gat_agg<1, 512><<<N, 256>>>(rowA, adjA, s, d, bufA, b2, finh, finl, 1536, 0);

    // ===== scatter means into fin[:,512:1536] =====
    mean_gather<<<N, 256>>>(rowL, eidL, xp2, finh, finl, 512);
    mean_gather<<<N, 256>>>(rowR, eidR, xp2, finh, finl, 1024);

    // ===== classifier =====
    {
        dim3 g(4, (N + 127) / 128);
        mma_gemm<1><<<g, 256, GEMM_DSM>>>(finh, finl, wc1h, wc1l, bc1, nullptr,
                                          hch, hcl, N, 512, 1536, 512, 512, 1);
    }
    {
        dim3 g(2, (N + 127) / 128);
        mma_gemm<0><<<g, 256, GEMM_DSM>>>(hch, hcl, wc2h, wc2l, bc2, out,
                                          nullptr, nullptr, N, 256, 512, NCLS, NCLS, 0);
    }
}